// round 16
// baseline (speedup 1.0000x reference)
#include <cuda_runtime.h>
#include <cuda_bf16.h>

typedef unsigned int u32;
typedef unsigned long long u64;

#define N_PTS 32768
#define N_CLU 512
#define DIM   1024
#define NBATCH 16
#define CHUNK2 8192
#define EPS   8.0f

// ---------------- scratch (device globals; no allocation) ----------------
__device__ u64 g_sortbuf[N_PTS];
__device__ int g_val[N_PTS];
__device__ __align__(16) float g_cent[N_CLU * DIM];
__device__ float g_csq[N_CLU];
__device__ __align__(16) float g_sums[N_CLU * DIM];
__device__ int g_counts[N_CLU];
__device__ int g_counts2[NBATCH * N_CLU];
__device__ __align__(16) float g_dist[N_PTS * N_CLU];   // approx distances
__device__ int g_unitv[16];                             // per-launch work counters
__device__ int g_rowc[256];                             // per-row-tile completion
// radix-select scratch
__device__ int g_hist[1024];
__device__ int g_cutoff;
__device__ int g_ccount;
__device__ u64 g_cand[1024];

// bf16 copies (X: once per launch, C: written by finalize/gather)
__device__ __align__(128) __nv_bfloat16 g_xb0[N_PTS * DIM];
__device__ __align__(128) __nv_bfloat16 g_cb0[N_CLU * DIM];

__device__ __forceinline__ u32 smem_u32(const void* p) {
    u32 a;
    asm("{ .reg .u64 t; cvta.to.shared.u64 t, %1; cvt.u32.u64 %0, t; }"
        : "=r"(a) : "l"(p));
    return a;
}

#define LDSM4(r, addr) \
    asm volatile("ldmatrix.sync.aligned.m8n8.x4.shared.b16 {%0,%1,%2,%3}, [%4];" \
        : "=r"((r)[0]), "=r"((r)[1]), "=r"((r)[2]), "=r"((r)[3]) : "r"(addr))

#define MMA16816(d, a, b0_, b1_) \
    asm volatile("mma.sync.aligned.m16n8k16.row.col.f32.bf16.bf16.f32 " \
        "{%0,%1,%2,%3}, {%4,%5,%6,%7}, {%8,%9}, {%0,%1,%2,%3};" \
        : "+f"((d)[0]), "+f"((d)[1]), "+f"((d)[2]), "+f"((d)[3]) \
        : "r"((a)[0]), "r"((a)[1]), "r"((a)[2]), "r"((a)[3]), "r"(b0_), "r"(b1_))

// ---------------- Threefry-2x32 (matches jax._src.prng) ----------------
__host__ __device__ inline void tf2x32(u32 k0, u32 k1, u32 x0, u32 x1,
                                       u32& o0, u32& o1) {
    u32 ks2 = k0 ^ k1 ^ 0x1BD11BDAu;
    x0 += k0; x1 += k1;
#define TF_R(r) { x0 += x1; x1 = (x1 << (r)) | (x1 >> (32 - (r))); x1 ^= x0; }
    TF_R(13) TF_R(15) TF_R(26) TF_R(6)
    x0 += k1;  x1 += ks2 + 1u;
    TF_R(17) TF_R(29) TF_R(16) TF_R(24)
    x0 += ks2; x1 += k0 + 2u;
    TF_R(13) TF_R(15) TF_R(26) TF_R(6)
    x0 += k0;  x1 += k1 + 3u;
    TF_R(17) TF_R(29) TF_R(16) TF_R(24)
    x0 += k1;  x1 += ks2 + 4u;
    TF_R(13) TF_R(15) TF_R(26) TF_R(6)
    x0 += ks2; x1 += k0 + 5u;
#undef TF_R
    o0 = x0; o1 = x1;
}

__global__ void gen_keys_kernel(u32 sk0, u32 sk1) {
    int i = blockIdx.x * blockDim.x + threadIdx.x;
    if (i >= N_PTS) return;
    u32 a, b;
    tf2x32(sk0, sk1, 0u, (u32)i, a, b);
    g_sortbuf[i] = ((u64)(a ^ b) << 32) | (u32)i;
}

// ---------------- bitonic sort (stable via (key,pos) composite) ----------------
__global__ void sort_local_big(void) {
    extern __shared__ u64 s[];
    int base = blockIdx.x * CHUNK2;
    for (int t = threadIdx.x; t < CHUNK2; t += blockDim.x) s[t] = g_sortbuf[base + t];
    __syncthreads();
    for (int k = 2; k <= CHUNK2; k <<= 1) {
        for (int j = k >> 1; j > 0; j >>= 1) {
            for (int t = threadIdx.x; t < CHUNK2 / 2; t += blockDim.x) {
                int i = ((t & ~(j - 1)) << 1) | (t & (j - 1));
                int l = i | j;
                bool asc = (((base + i) & k) == 0);
                u64 x = s[i], y = s[l];
                if ((x > y) == asc) { s[i] = y; s[l] = x; }
            }
            __syncthreads();
        }
    }
    for (int t = threadIdx.x; t < CHUNK2; t += blockDim.x) g_sortbuf[base + t] = s[t];
}

__global__ void sort_global(int k, int j) {
    int t = blockIdx.x * blockDim.x + threadIdx.x;
    int i = ((t & ~(j - 1)) << 1) | (t & (j - 1));
    int l = i | j;
    bool asc = ((i & k) == 0);
    u64 x = g_sortbuf[i], y = g_sortbuf[l];
    if ((x > y) == asc) { g_sortbuf[i] = y; g_sortbuf[l] = x; }
}

__global__ void sort_merge_big(int k) {
    extern __shared__ u64 s[];
    int base = blockIdx.x * CHUNK2;
    bool asc = ((base & k) == 0);
    for (int t = threadIdx.x; t < CHUNK2; t += blockDim.x) s[t] = g_sortbuf[base + t];
    __syncthreads();
    for (int j = CHUNK2 / 2; j > 0; j >>= 1) {
        for (int t = threadIdx.x; t < CHUNK2 / 2; t += blockDim.x) {
            int i = ((t & ~(j - 1)) << 1) | (t & (j - 1));
            int l = i | j;
            u64 x = s[i], y = s[l];
            if ((x > y) == asc) { s[i] = y; s[l] = x; }
        }
        __syncthreads();
    }
    for (int t = threadIdx.x; t < CHUNK2; t += blockDim.x) g_sortbuf[base + t] = s[t];
}

__global__ void extract_val(void) {
    int i = blockIdx.x * blockDim.x + threadIdx.x;
    if (i < N_PTS) g_val[i] = (int)(g_sortbuf[i] & 0xFFFFFFFFu);
}

// ---------------- round-2: radix-select of the 512 smallest composites ------
__global__ void sel_zero(void) {
    int t = threadIdx.x;
    g_hist[t] = 0;
    if (t == 0) g_ccount = 0;
}

__global__ void sel_hist(void) {
    int i = blockIdx.x * blockDim.x + threadIdx.x;
    u64 v = g_sortbuf[i];
    atomicAdd(&g_hist[(int)(v >> 54)], 1);
}

__global__ void sel_scan(void) {        // 1 block, 1024 threads
    __shared__ int s[1024];
    __shared__ int h[1024];
    int t = threadIdx.x;
    h[t] = g_hist[t];
    s[t] = h[t];
    __syncthreads();
    for (int o = 1; o < 1024; o <<= 1) {
        int v = (t >= o) ? s[t - o] : 0;
        __syncthreads();
        s[t] += v;
        __syncthreads();
    }
    if (s[t] >= 512 && (s[t] - h[t]) < 512) g_cutoff = t;
}

__global__ void sel_compact(void) {
    int i = blockIdx.x * blockDim.x + threadIdx.x;
    u64 v = g_sortbuf[i];
    if ((int)(v >> 54) <= g_cutoff) {
        int p = atomicAdd(&g_ccount, 1);
        if (p < 1024) g_cand[p] = v;
    }
}

__global__ void sel_sort(void) {        // 1 block, 512 threads: sort 1024 padded
    __shared__ u64 s[1024];
    int t = threadIdx.x;
    int cnt = g_ccount; if (cnt > 1024) cnt = 1024;
    for (int i = t; i < 1024; i += 512)
        s[i] = (i < cnt) ? g_cand[i] : ~0ull;
    __syncthreads();
    for (int k = 2; k <= 1024; k <<= 1) {
        for (int j = k >> 1; j > 0; j >>= 1) {
            int i = ((t & ~(j - 1)) << 1) | (t & (j - 1));
            int l = i | j;
            bool asc = ((i & k) == 0);
            u64 x = s[i], y = s[l];
            if ((x > y) == asc) { s[i] = y; s[l] = x; }
            __syncthreads();
        }
    }
    if (t < 512) g_sortbuf[t] = s[t];
}

// gather centroids + csq (strided loop, original order) + bf16 copy
__global__ void gather_init(const float* __restrict__ X) {
    int c = blockIdx.x, t = threadIdx.x;
    int pos = (int)(g_sortbuf[c] & 0xFFFFFFFFu);
    int src = g_val[pos];
    float4 v = ((const float4*)&X[(size_t)src * DIM])[t];
    ((float4*)&g_cent[(size_t)c * DIM])[t] = v;
    __nv_bfloat16* cb = &g_cb0[(size_t)c * DIM + t * 4];
    cb[0] = __float2bfloat16_rn(v.x); cb[1] = __float2bfloat16_rn(v.y);
    cb[2] = __float2bfloat16_rn(v.z); cb[3] = __float2bfloat16_rn(v.w);
    __shared__ float red[256];
    __syncthreads();
    const float* row = &g_cent[(size_t)c * DIM];
    float s = 0.f;
    for (int k = t; k < DIM; k += 256) { float vv = row[k]; s += vv * vv; }
    red[t] = s; __syncthreads();
    for (int o = 128; o > 0; o >>= 1) {
        if (t < o) red[t] += red[t + o];
        __syncthreads();
    }
    if (t == 0) g_csq[c] = red[0];
}

__global__ void convert_x(const float* __restrict__ X) {
    int i = blockIdx.x * blockDim.x + threadIdx.x;
    g_xb0[i] = __float2bfloat16_rn(X[i]);
}

__global__ void zero_sums(void) {
    int t = blockIdx.x * blockDim.x + threadIdx.x;
    if (t < N_CLU * DIM) g_sums[t] = 0.f;
    if (t < N_CLU) g_counts[t] = 0;
    if (t < 16) g_unitv[t] = 0;
    if (t < 256) g_rowc[t] = 0;
}

// ---------------- refine helper (exact fp32 rescue) ----------------
__device__ __forceinline__ int refine_pick(int wip, int lane,
                                           const float* __restrict__ X,
                                           float4* xr) {
    const float* drow = &g_dist[(size_t)wip * N_CLU];
    float d[16];
    float m = 3.4e38f;
#pragma unroll
    for (int k = 0; k < 16; k++) { d[k] = drow[k * 32 + lane]; m = fminf(m, d[k]); }
#pragma unroll
    for (int o = 16; o; o >>= 1) m = fminf(m, __shfl_xor_sync(0xFFFFFFFFu, m, o));
    float thr = m + EPS;

    const float4* xrow4 = (const float4*)&X[(size_t)wip * DIM];
#pragma unroll
    for (int q = 0; q < 8; q++) xr[q] = xrow4[lane + 32 * q];

    u32 bal[16];
    int cnt = 0;
#pragma unroll
    for (int k = 0; k < 16; k++) {
        bal[k] = __ballot_sync(0xFFFFFFFFu, d[k] < thr);
        cnt += __popc(bal[k]);
    }

    int bidx = N_CLU;
    if (cnt == 1) {
#pragma unroll
        for (int k = 0; k < 16; k++)
            if (bal[k]) bidx = k * 32 + __ffs(bal[k]) - 1;
    } else {
        float best = 3.4e38f;
#pragma unroll 1
        for (int k = 0; k < 16; k++) {
            u32 mask = bal[k];
            while (mask) {
                int src = __ffs(mask) - 1;
                mask &= mask - 1;
                int c = k * 32 + src;
                const float4* crow4 = (const float4*)&g_cent[(size_t)c * DIM];
                float s = 0.f;
#pragma unroll
                for (int q = 0; q < 8; q++) {
                    float4 cv = crow4[lane + 32 * q];
                    s += xr[q].x * cv.x + xr[q].y * cv.y + xr[q].z * cv.z + xr[q].w * cv.w;
                }
#pragma unroll
                for (int o = 16; o; o >>= 1) s += __shfl_xor_sync(0xFFFFFFFFu, s, o);
                float dist = g_csq[c] - 2.0f * s;
                if (dist < best || (dist == best && c < bidx)) { best = dist; bidx = c; }
            }
        }
    }
    return bidx;
}

// ---------------- Phase 1+2 fused: persistent HMMA dist + tile-completion refine
// __launch_bounds__(256, 2) caps regs at 128/thread so 2 CTAs stay resident
// per SM (R15 regression = occupancy drop to 1). Refine-path state spills to
// local; that path is LSU-bound and overlaps the other CTA's tensor work.
#define SSTR 40
#define NCH 32
#define N_UNITS 1024
#define DIST_GRID 296

__global__ void __launch_bounds__(256, 2) dist_refine(int itp,
                                                      const float* __restrict__ X,
                                                      float* __restrict__ outp,
                                                      int final_it) {
    __shared__ __nv_bfloat16 sA[2][128 * SSTR];
    __shared__ __nv_bfloat16 sB[2][128 * SSTR];
    __shared__ float s_csq[N_CLU];
    __shared__ int s_unit;
    __shared__ int s_old;

    int tid = threadIdx.x, wid = tid >> 5, lid = tid & 31;
    for (int j = tid; j < N_CLU; j += 256) s_csq[j] = g_csq[j];

    int ar0 = tid >> 2,          as0 = (tid & 3);
    int ar1 = (tid + 256) >> 2,  as1 = ((tid + 256) & 3);

    u32 sAb = smem_u32(sA), sBb = smem_u32(sB);
    int l16 = lid & 15, lh = lid >> 4;
    u32 aoff = (u32)(((wid * 16 + l16) * SSTR + lh * 8) * 2);
    int bm = lid >> 3, bl = lid & 7;
    u32 boff = (u32)(((((bm >> 1) * 8) + bl) * SSTR + (bm & 1) * 8) * 2);

    int erow = lid >> 2;
    int ecol = (lid & 3) * 2;

    for (;;) {
        __syncthreads();
        if (tid == 0) s_unit = atomicAdd(&g_unitv[itp], 1);
        __syncthreads();
        int u = s_unit;
        if (u >= N_UNITS) break;
        int row0 = (u >> 2) * 128;
        int col0 = (u & 3) * 128;

        float acc[16][4];
#pragma unroll
        for (int t = 0; t < 16; t++)
#pragma unroll
            for (int i = 0; i < 4; i++) acc[t][i] = 0.f;

        uint4 ra0, ra1, rb0, rb1;
        ra0 = *(const uint4*)(g_xb0 + (size_t)(row0 + ar0) * DIM + as0 * 8);
        ra1 = *(const uint4*)(g_xb0 + (size_t)(row0 + ar1) * DIM + as1 * 8);
        rb0 = *(const uint4*)(g_cb0 + (size_t)(col0 + ar0) * DIM + as0 * 8);
        rb1 = *(const uint4*)(g_cb0 + (size_t)(col0 + ar1) * DIM + as1 * 8);
        *(uint4*)&sA[0][ar0 * SSTR + as0 * 8] = ra0;
        *(uint4*)&sA[0][ar1 * SSTR + as1 * 8] = ra1;
        *(uint4*)&sB[0][ar0 * SSTR + as0 * 8] = rb0;
        *(uint4*)&sB[0][ar1 * SSTR + as1 * 8] = rb1;
        __syncthreads();

        for (int c = 0; c < NCH; c++) {
            int buf = c & 1;
            bool more = (c + 1 < NCH);
            if (more) {
                int kk = (c + 1) << 5;
                ra0 = *(const uint4*)(g_xb0 + (size_t)(row0 + ar0) * DIM + kk + as0 * 8);
                ra1 = *(const uint4*)(g_xb0 + (size_t)(row0 + ar1) * DIM + kk + as1 * 8);
                rb0 = *(const uint4*)(g_cb0 + (size_t)(col0 + ar0) * DIM + kk + as0 * 8);
                rb1 = *(const uint4*)(g_cb0 + (size_t)(col0 + ar1) * DIM + kk + as1 * 8);
            }
            u32 abase = sAb + buf * (128 * SSTR * 2);
            u32 bbase = sBb + buf * (128 * SSTR * 2);
            u32 afr0[4], afr1[4];
            LDSM4(afr0, abase + aoff);
            LDSM4(afr1, abase + aoff + 32);
#pragma unroll
            for (int p = 0; p < 8; p++) {
                u32 bb = bbase + boff + (u32)(p * 16 * SSTR * 2);
                u32 bf[4];
                LDSM4(bf, bb);
                MMA16816(acc[2 * p],     afr0, bf[0], bf[1]);
                MMA16816(acc[2 * p + 1], afr0, bf[2], bf[3]);
                LDSM4(bf, bb + 32);
                MMA16816(acc[2 * p],     afr1, bf[0], bf[1]);
                MMA16816(acc[2 * p + 1], afr1, bf[2], bf[3]);
            }
            if (more) {
                __syncthreads();
                int nb = buf ^ 1;
                *(uint4*)&sA[nb][ar0 * SSTR + as0 * 8] = ra0;
                *(uint4*)&sA[nb][ar1 * SSTR + as1 * 8] = ra1;
                *(uint4*)&sB[nb][ar0 * SSTR + as0 * 8] = rb0;
                *(uint4*)&sB[nb][ar1 * SSTR + as1 * 8] = rb1;
                __syncthreads();
            }
        }
        // store approx distances csq - 2*dot
        {
            int r = row0 + wid * 16 + erow;
#pragma unroll
            for (int t = 0; t < 16; t++) {
                int cbase = col0 + t * 8 + ecol;
                float cs0 = s_csq[cbase], cs1 = s_csq[cbase + 1];
                float2 v0 = make_float2(cs0 - 2.0f * acc[t][0], cs1 - 2.0f * acc[t][1]);
                float2 v1 = make_float2(cs0 - 2.0f * acc[t][2], cs1 - 2.0f * acc[t][3]);
                *(float2*)&g_dist[(size_t)r * N_CLU + cbase] = v0;
                *(float2*)&g_dist[(size_t)(r + 8) * N_CLU + cbase] = v1;
            }
        }
        // tile-completion: last finisher refines this row tile
        __syncthreads();
        if (tid == 0) {
            __threadfence();
            s_old = atomicAdd(&g_rowc[u >> 2], 1);
        }
        __syncthreads();
        if (s_old == 3) {
            __threadfence();   // make other units' dist stores visible
#pragma unroll 1
            for (int pi = 0; pi < 16; pi++) {
                int wip = row0 + wid * 16 + pi;
                float4 xr[8];
                int bidx = refine_pick(wip, lid, X, xr);
                if (final_it) {
                    int s = (wip >> 11) * N_CLU + bidx;
                    float4* dst = (float4*)&outp[(size_t)s * DIM];
#pragma unroll
                    for (int q = 0; q < 8; q++) atomicAdd(&dst[lid + 32 * q], xr[q]);
                    if (lid == 0) atomicAdd(&g_counts2[s], 1);
                } else {
                    float4* dst = (float4*)&g_sums[(size_t)bidx * DIM];
#pragma unroll
                    for (int q = 0; q < 8; q++) atomicAdd(&dst[lid + 32 * q], xr[q]);
                    if (lid == 0) atomicAdd(&g_counts[bidx], 1);
                }
            }
            __syncthreads();
            if (tid == 0) g_rowc[u >> 2] = 0;   // ready for next launch
        }
    }
}

// ---------------- centroid update (+ csq + bf16 + zero for next iter) --------
__global__ void finalize_cent(void) {
    int c = blockIdx.x, t = threadIdx.x;
    int cnt = g_counts[c];
    float fc = (float)cnt;
    float4 sv = ((const float4*)&g_sums[(size_t)c * DIM])[t];
    float4 cv;
    if (cnt > 0) { cv.x = sv.x / fc; cv.y = sv.y / fc; cv.z = sv.z / fc; cv.w = sv.w / fc; }
    else cv = make_float4(0.f, 0.f, 0.f, 0.f);
    ((float4*)&g_cent[(size_t)c * DIM])[t] = cv;
    ((float4*)&g_sums[(size_t)c * DIM])[t] = make_float4(0.f, 0.f, 0.f, 0.f);
    __nv_bfloat16* cb = &g_cb0[(size_t)c * DIM + t * 4];
    cb[0] = __float2bfloat16_rn(cv.x); cb[1] = __float2bfloat16_rn(cv.y);
    cb[2] = __float2bfloat16_rn(cv.z); cb[3] = __float2bfloat16_rn(cv.w);

    __shared__ float red[256];
    __syncthreads();
    if (t == 0) g_counts[c] = 0;
    // csq: identical order to original csq_kernel (strided read of g_cent)
    const float* row = &g_cent[(size_t)c * DIM];
    float s = 0.f;
    for (int k = t; k < DIM; k += 256) { float v = row[k]; s += v * v; }
    red[t] = s; __syncthreads();
    for (int o = 128; o > 0; o >>= 1) {
        if (t < o) red[t] += red[t + o];
        __syncthreads();
    }
    if (t == 0) g_csq[c] = red[0];
}

// ---------------- output ----------------
__global__ void zero_out(float* __restrict__ out) {
    int t = blockIdx.x * blockDim.x + threadIdx.x;
    out[t] = 0.f;
    if (t < NBATCH * N_CLU) g_counts2[t] = 0;
}

__global__ void div_out(float* __restrict__ out) {
    int s = blockIdx.x;
    int cnt = g_counts2[s];
    if (cnt <= 0) return;
    float fc = (float)cnt;
    for (int k = threadIdx.x; k < DIM; k += 256)
        out[(size_t)s * DIM + k] /= fc;
}

// ---------------- driver ----------------
static void run_full_sort() {
    sort_local_big<<<N_PTS / CHUNK2, 1024, CHUNK2 * 8>>>();
    sort_global<<<N_PTS / 2 / 256, 256>>>(16384, 8192);
    sort_merge_big<<<N_PTS / CHUNK2, 1024, CHUNK2 * 8>>>(16384);
    sort_global<<<N_PTS / 2 / 256, 256>>>(32768, 16384);
    sort_global<<<N_PTS / 2 / 256, 256>>>(32768, 8192);
    sort_merge_big<<<N_PTS / CHUNK2, 1024, CHUNK2 * 8>>>(32768);
}

extern "C" void kernel_launch(void* const* d_in, const int* in_sizes, int n_in,
                              void* d_out, int out_size) {
    (void)in_sizes; (void)n_in; (void)out_size;
    const float* X = (const float*)d_in[0];
    float* out = (float*)d_out;

    cudaFuncSetAttribute(sort_local_big,
                         cudaFuncAttributeMaxDynamicSharedMemorySize, CHUNK2 * 8);
    cudaFuncSetAttribute(sort_merge_big,
                         cudaFuncAttributeMaxDynamicSharedMemorySize, CHUNK2 * 8);

    // jax.random.key(42): partitionable threefry shuffle, 2 rounds
    u32 K1a, K1b, S1a, S1b, S2a, S2b;
    tf2x32(0u, 42u, 0u, 0u, K1a, K1b);
    tf2x32(0u, 42u, 0u, 1u, S1a, S1b);
    tf2x32(K1a, K1b, 0u, 1u, S2a, S2b);

    // round 1: full sort (need the full permutation)
    gen_keys_kernel<<<N_PTS / 256, 256>>>(S1a, S1b);
    run_full_sort();
    extract_val<<<N_PTS / 256, 256>>>();
    // round 2: only the 512 smallest composites matter -> radix-select
    gen_keys_kernel<<<N_PTS / 256, 256>>>(S2a, S2b);
    sel_zero<<<1, 1024>>>();
    sel_hist<<<N_PTS / 256, 256>>>();
    sel_scan<<<1, 1024>>>();
    sel_compact<<<N_PTS / 256, 256>>>();
    sel_sort<<<1, 512>>>();

    gather_init<<<N_CLU, 256>>>(X);
    convert_x<<<N_PTS, 1024>>>(X);
    zero_sums<<<(N_CLU * DIM) / 256, 256>>>();

    for (int it = 0; it < 9; it++) {
        dist_refine<<<DIST_GRID, 256>>>(it, X, out, 0);
        finalize_cent<<<N_CLU, 256>>>();
    }
    // iteration 10: refine scatters straight into the per-batch output
    zero_out<<<(NBATCH * N_CLU * DIM) / 1024, 1024>>>(out);
    dist_refine<<<DIST_GRID, 256>>>(9, X, out, 1);
    div_out<<<NBATCH * N_CLU, 256>>>(out);
}

// round 17
// speedup vs baseline: 1.2368x; 1.2368x over previous
#include <cuda_runtime.h>
#include <cuda_bf16.h>

typedef unsigned int u32;
typedef unsigned long long u64;

#define N_PTS 32768
#define N_CLU 512
#define DIM   1024
#define NBATCH 16
#define EPS   8.0f

// ---------------- scratch (device globals; no allocation) ----------------
__device__ u64 g_sortbuf[N_PTS];
__device__ __align__(16) float g_cent[N_CLU * DIM];
__device__ float g_csq[N_CLU];
__device__ int g_idx[N_PTS];
__device__ __align__(16) float g_sums[N_CLU * DIM];
__device__ int g_counts[N_CLU];
__device__ int g_counts2[NBATCH * N_CLU];
__device__ __align__(16) float g_dist[N_PTS * N_CLU];   // approx distances
__device__ int g_unitv[16];                             // per-launch work counters
// round-1 bucket-rank scratch
__device__ int g_h1[1024];
__device__ int g_b1[1025];
__device__ int g_c1[1024];
__device__ u64 g_bucket[N_PTS];
// round-2 radix-select scratch
__device__ int g_hist[1024];
__device__ int g_cutoff;
__device__ int g_ccount;
__device__ u64 g_cand[1024];

// bf16 copies (X: once per launch, C: written by finalize/gather)
__device__ __align__(128) __nv_bfloat16 g_xb0[N_PTS * DIM];
__device__ __align__(128) __nv_bfloat16 g_cb0[N_CLU * DIM];

__device__ __forceinline__ u32 smem_u32(const void* p) {
    u32 a;
    asm("{ .reg .u64 t; cvta.to.shared.u64 t, %1; cvt.u32.u64 %0, t; }"
        : "=r"(a) : "l"(p));
    return a;
}

#define LDSM4(r, addr) \
    asm volatile("ldmatrix.sync.aligned.m8n8.x4.shared.b16 {%0,%1,%2,%3}, [%4];" \
        : "=r"((r)[0]), "=r"((r)[1]), "=r"((r)[2]), "=r"((r)[3]) : "r"(addr))

#define MMA16816(d, a, b0_, b1_) \
    asm volatile("mma.sync.aligned.m16n8k16.row.col.f32.bf16.bf16.f32 " \
        "{%0,%1,%2,%3}, {%4,%5,%6,%7}, {%8,%9}, {%0,%1,%2,%3};" \
        : "+f"((d)[0]), "+f"((d)[1]), "+f"((d)[2]), "+f"((d)[3]) \
        : "r"((a)[0]), "r"((a)[1]), "r"((a)[2]), "r"((a)[3]), "r"(b0_), "r"(b1_))

// ---------------- Threefry-2x32 (matches jax._src.prng) ----------------
__host__ __device__ inline void tf2x32(u32 k0, u32 k1, u32 x0, u32 x1,
                                       u32& o0, u32& o1) {
    u32 ks2 = k0 ^ k1 ^ 0x1BD11BDAu;
    x0 += k0; x1 += k1;
#define TF_R(r) { x0 += x1; x1 = (x1 << (r)) | (x1 >> (32 - (r))); x1 ^= x0; }
    TF_R(13) TF_R(15) TF_R(26) TF_R(6)
    x0 += k1;  x1 += ks2 + 1u;
    TF_R(17) TF_R(29) TF_R(16) TF_R(24)
    x0 += ks2; x1 += k0 + 2u;
    TF_R(13) TF_R(15) TF_R(26) TF_R(6)
    x0 += k0;  x1 += k1 + 3u;
    TF_R(17) TF_R(29) TF_R(16) TF_R(24)
    x0 += k1;  x1 += ks2 + 4u;
    TF_R(13) TF_R(15) TF_R(26) TF_R(6)
    x0 += ks2; x1 += k0 + 5u;
#undef TF_R
    o0 = x0; o1 = x1;
}

__global__ void gen_keys_kernel(u32 sk0, u32 sk1) {
    int i = blockIdx.x * blockDim.x + threadIdx.x;
    if (i >= N_PTS) return;
    u32 a, b;
    tf2x32(sk0, sk1, 0u, (u32)i, a, b);
    g_sortbuf[i] = ((u64)(a ^ b) << 32) | (u32)i;
}

// ---------------- round-1: bucket by top-10 bits, rank-on-demand ------------
__global__ void r1_zero(void) {
    int t = threadIdx.x;
    g_h1[t] = 0; g_c1[t] = 0;
}

__global__ void r1_hist(void) {
    int i = blockIdx.x * blockDim.x + threadIdx.x;
    atomicAdd(&g_h1[(int)(g_sortbuf[i] >> 54)], 1);
}

__global__ void r1_scan(void) {         // 1 block, 1024 threads: exclusive scan
    __shared__ int s[1024];
    int t = threadIdx.x;
    int h = g_h1[t];
    s[t] = h;
    __syncthreads();
    for (int o = 1; o < 1024; o <<= 1) {
        int v = (t >= o) ? s[t - o] : 0;
        __syncthreads();
        s[t] += v;
        __syncthreads();
    }
    g_b1[t] = s[t] - h;                 // exclusive
    if (t == 1023) g_b1[1024] = N_PTS;
}

__global__ void r1_scatter(void) {
    int i = blockIdx.x * blockDim.x + threadIdx.x;
    u64 v = g_sortbuf[i];
    int b = (int)(v >> 54);
    int slot = g_b1[b] + atomicAdd(&g_c1[b], 1);
    g_bucket[slot] = v;                 // intra-bin order arbitrary (rank fixes it)
}

// ---------------- round-2: radix-select of the 512 smallest composites ------
__global__ void sel_zero(void) {
    int t = threadIdx.x;
    g_hist[t] = 0;
    if (t == 0) g_ccount = 0;
}

__global__ void sel_hist(void) {
    int i = blockIdx.x * blockDim.x + threadIdx.x;
    u64 v = g_sortbuf[i];
    atomicAdd(&g_hist[(int)(v >> 54)], 1);
}

__global__ void sel_scan(void) {        // 1 block, 1024 threads
    __shared__ int s[1024];
    __shared__ int h[1024];
    int t = threadIdx.x;
    h[t] = g_hist[t];
    s[t] = h[t];
    __syncthreads();
    for (int o = 1; o < 1024; o <<= 1) {
        int v = (t >= o) ? s[t - o] : 0;
        __syncthreads();
        s[t] += v;
        __syncthreads();
    }
    if (s[t] >= 512 && (s[t] - h[t]) < 512) g_cutoff = t;
}

__global__ void sel_compact(void) {
    int i = blockIdx.x * blockDim.x + threadIdx.x;
    u64 v = g_sortbuf[i];
    if ((int)(v >> 54) <= g_cutoff) {
        int p = atomicAdd(&g_ccount, 1);
        if (p < 1024) g_cand[p] = v;
    }
}

__global__ void sel_sort(void) {        // 1 block, 512 threads: sort 1024 padded
    __shared__ u64 s[1024];
    int t = threadIdx.x;
    int cnt = g_ccount; if (cnt > 1024) cnt = 1024;
    for (int i = t; i < 1024; i += 512)
        s[i] = (i < cnt) ? g_cand[i] : ~0ull;
    __syncthreads();
    for (int k = 2; k <= 1024; k <<= 1) {
        for (int j = k >> 1; j > 0; j >>= 1) {
            int i = ((t & ~(j - 1)) << 1) | (t & (j - 1));
            int l = i | j;
            bool asc = ((i & k) == 0);
            u64 x = s[i], y = s[l];
            if ((x > y) == asc) { s[i] = y; s[l] = x; }
            __syncthreads();
        }
    }
    if (t < 512) g_sortbuf[t] = s[t];
}

// gather centroids: rank-lookup of v1[pos] in the round-1 bucket, then
// csq (strided loop, original order) + bf16 copy
__global__ void gather_init(const float* __restrict__ X) {
    int c = blockIdx.x, t = threadIdx.x;
    int pos = (int)(g_sortbuf[c] & 0xFFFFFFFFu);

    // binary search bin: g_b1[b] <= pos < g_b1[b+1]
    int lo = 0, hi = 1024;
    while (hi - lo > 1) {
        int mid = (lo + hi) >> 1;
        if (g_b1[mid] <= pos) lo = mid; else hi = mid;
    }
    int base = g_b1[lo], n = g_b1[lo + 1] - base, target = pos - base;

    __shared__ u64 s_e[256];
    __shared__ int s_src;
    if (t < n) s_e[t] = g_bucket[base + t];
    __syncthreads();
    if (t < n) {
        u64 e = s_e[t];
        int rank = 0;
        for (int j = 0; j < n; j++) rank += (s_e[j] < e);
        if (rank == target) s_src = (int)(e & 0xFFFFFFFFu);
    }
    __syncthreads();
    int src = s_src;

    float4 v = ((const float4*)&X[(size_t)src * DIM])[t];
    ((float4*)&g_cent[(size_t)c * DIM])[t] = v;
    __nv_bfloat16* cb = &g_cb0[(size_t)c * DIM + t * 4];
    cb[0] = __float2bfloat16_rn(v.x); cb[1] = __float2bfloat16_rn(v.y);
    cb[2] = __float2bfloat16_rn(v.z); cb[3] = __float2bfloat16_rn(v.w);
    __shared__ float red[256];
    __syncthreads();
    const float* row = &g_cent[(size_t)c * DIM];
    float s = 0.f;
    for (int k = t; k < DIM; k += 256) { float vv = row[k]; s += vv * vv; }
    red[t] = s; __syncthreads();
    for (int o = 128; o > 0; o >>= 1) {
        if (t < o) red[t] += red[t + o];
        __syncthreads();
    }
    if (t == 0) g_csq[c] = red[0];
}

__global__ void convert_x(const float* __restrict__ X) {
    int i = blockIdx.x * blockDim.x + threadIdx.x;
    g_xb0[i] = __float2bfloat16_rn(X[i]);
}

__global__ void zero_sums(void) {
    int t = blockIdx.x * blockDim.x + threadIdx.x;
    if (t < N_CLU * DIM) g_sums[t] = 0.f;
    if (t < N_CLU) g_counts[t] = 0;
    if (t < 16) g_unitv[t] = 0;
}

// ---------------- Phase 1: persistent bf16 HMMA approx distance matrix ----------
// 296 persistent CTAs; 1024 work units = (row-tile 0..255, col-pass 0..3).
#define SSTR 40
#define NCH 32
#define N_UNITS 1024
#define DIST_GRID 296

__global__ void __launch_bounds__(256) dist_hmma(int itp) {
    __shared__ __nv_bfloat16 sA[2][128 * SSTR];
    __shared__ __nv_bfloat16 sB[2][128 * SSTR];
    __shared__ float s_csq[N_CLU];
    __shared__ int s_unit;

    int tid = threadIdx.x, wid = tid >> 5, lid = tid & 31;
    for (int j = tid; j < N_CLU; j += 256) s_csq[j] = g_csq[j];

    int ar0 = tid >> 2,          as0 = (tid & 3);
    int ar1 = (tid + 256) >> 2,  as1 = ((tid + 256) & 3);

    u32 sAb = smem_u32(sA), sBb = smem_u32(sB);
    int l16 = lid & 15, lh = lid >> 4;
    u32 aoff = (u32)(((wid * 16 + l16) * SSTR + lh * 8) * 2);
    int bm = lid >> 3, bl = lid & 7;
    u32 boff = (u32)(((((bm >> 1) * 8) + bl) * SSTR + (bm & 1) * 8) * 2);

    int erow = lid >> 2;
    int ecol = (lid & 3) * 2;

    for (;;) {
        __syncthreads();
        if (tid == 0) s_unit = atomicAdd(&g_unitv[itp], 1);
        __syncthreads();
        int u = s_unit;
        if (u >= N_UNITS) break;
        int row0 = (u >> 2) * 128;
        int col0 = (u & 3) * 128;

        float acc[16][4];
#pragma unroll
        for (int t = 0; t < 16; t++)
#pragma unroll
            for (int i = 0; i < 4; i++) acc[t][i] = 0.f;

        uint4 ra0, ra1, rb0, rb1;
        ra0 = *(const uint4*)(g_xb0 + (size_t)(row0 + ar0) * DIM + as0 * 8);
        ra1 = *(const uint4*)(g_xb0 + (size_t)(row0 + ar1) * DIM + as1 * 8);
        rb0 = *(const uint4*)(g_cb0 + (size_t)(col0 + ar0) * DIM + as0 * 8);
        rb1 = *(const uint4*)(g_cb0 + (size_t)(col0 + ar1) * DIM + as1 * 8);
        *(uint4*)&sA[0][ar0 * SSTR + as0 * 8] = ra0;
        *(uint4*)&sA[0][ar1 * SSTR + as1 * 8] = ra1;
        *(uint4*)&sB[0][ar0 * SSTR + as0 * 8] = rb0;
        *(uint4*)&sB[0][ar1 * SSTR + as1 * 8] = rb1;
        __syncthreads();

        for (int c = 0; c < NCH; c++) {
            int buf = c & 1;
            bool more = (c + 1 < NCH);
            if (more) {
                int kk = (c + 1) << 5;
                ra0 = *(const uint4*)(g_xb0 + (size_t)(row0 + ar0) * DIM + kk + as0 * 8);
                ra1 = *(const uint4*)(g_xb0 + (size_t)(row0 + ar1) * DIM + kk + as1 * 8);
                rb0 = *(const uint4*)(g_cb0 + (size_t)(col0 + ar0) * DIM + kk + as0 * 8);
                rb1 = *(const uint4*)(g_cb0 + (size_t)(col0 + ar1) * DIM + kk + as1 * 8);
            }
            u32 abase = sAb + buf * (128 * SSTR * 2);
            u32 bbase = sBb + buf * (128 * SSTR * 2);
            u32 afr0[4], afr1[4];
            LDSM4(afr0, abase + aoff);
            LDSM4(afr1, abase + aoff + 32);
#pragma unroll
            for (int p = 0; p < 8; p++) {
                u32 bb = bbase + boff + (u32)(p * 16 * SSTR * 2);
                u32 bf[4];
                LDSM4(bf, bb);
                MMA16816(acc[2 * p],     afr0, bf[0], bf[1]);
                MMA16816(acc[2 * p + 1], afr0, bf[2], bf[3]);
                LDSM4(bf, bb + 32);
                MMA16816(acc[2 * p],     afr1, bf[0], bf[1]);
                MMA16816(acc[2 * p + 1], afr1, bf[2], bf[3]);
            }
            if (more) {
                __syncthreads();
                int nb = buf ^ 1;
                *(uint4*)&sA[nb][ar0 * SSTR + as0 * 8] = ra0;
                *(uint4*)&sA[nb][ar1 * SSTR + as1 * 8] = ra1;
                *(uint4*)&sB[nb][ar0 * SSTR + as0 * 8] = rb0;
                *(uint4*)&sB[nb][ar1 * SSTR + as1 * 8] = rb1;
                __syncthreads();
            }
        }
        // store approx distances csq - 2*dot
        {
            int r = row0 + wid * 16 + erow;
#pragma unroll
            for (int t = 0; t < 16; t++) {
                int cbase = col0 + t * 8 + ecol;
                float cs0 = s_csq[cbase], cs1 = s_csq[cbase + 1];
                float2 v0 = make_float2(cs0 - 2.0f * acc[t][0], cs1 - 2.0f * acc[t][1]);
                float2 v1 = make_float2(cs0 - 2.0f * acc[t][2], cs1 - 2.0f * acc[t][3]);
                *(float2*)&g_dist[(size_t)r * N_CLU + cbase] = v0;
                *(float2*)&g_dist[(size_t)(r + 8) * N_CLU + cbase] = v1;
            }
        }
    }
}

// ---------------- Phase 2 helpers ----------------
__device__ __forceinline__ int refine_pick(int wip, int lane,
                                           const float* __restrict__ X,
                                           float4* xr) {
    const float* drow = &g_dist[(size_t)wip * N_CLU];
    float d[16];
    float m = 3.4e38f;
#pragma unroll
    for (int k = 0; k < 16; k++) { d[k] = drow[k * 32 + lane]; m = fminf(m, d[k]); }
#pragma unroll
    for (int o = 16; o; o >>= 1) m = fminf(m, __shfl_xor_sync(0xFFFFFFFFu, m, o));
    float thr = m + EPS;

    const float4* xrow4 = (const float4*)&X[(size_t)wip * DIM];
#pragma unroll
    for (int q = 0; q < 8; q++) xr[q] = xrow4[lane + 32 * q];

    u32 bal[16];
    int cnt = 0;
#pragma unroll
    for (int k = 0; k < 16; k++) {
        bal[k] = __ballot_sync(0xFFFFFFFFu, d[k] < thr);
        cnt += __popc(bal[k]);
    }

    int bidx = N_CLU;
    if (cnt == 1) {
#pragma unroll
        for (int k = 0; k < 16; k++)
            if (bal[k]) bidx = k * 32 + __ffs(bal[k]) - 1;
    } else {
        float best = 3.4e38f;
#pragma unroll 1
        for (int k = 0; k < 16; k++) {
            u32 mask = bal[k];
            while (mask) {
                int src = __ffs(mask) - 1;
                mask &= mask - 1;
                int c = k * 32 + src;
                const float4* crow4 = (const float4*)&g_cent[(size_t)c * DIM];
                float s = 0.f;
#pragma unroll
                for (int q = 0; q < 8; q++) {
                    float4 cv = crow4[lane + 32 * q];
                    s += xr[q].x * cv.x + xr[q].y * cv.y + xr[q].z * cv.z + xr[q].w * cv.w;
                }
#pragma unroll
                for (int o = 16; o; o >>= 1) s += __shfl_xor_sync(0xFFFFFFFFu, s, o);
                float dist = g_csq[c] - 2.0f * s;
                if (dist < best || (dist == best && c < bidx)) { best = dist; bidx = c; }
            }
        }
    }
    return bidx;
}

// iterations 1..9: scatter into g_sums
__global__ void __launch_bounds__(256) refine_scatter(const float* __restrict__ X) {
    int wip = (blockIdx.x * blockDim.x + threadIdx.x) >> 5;
    int lane = threadIdx.x & 31;
    float4 xr[8];
    int bidx = refine_pick(wip, lane, X, xr);
    if (lane == 0) g_idx[wip] = bidx;
    float4* dst = (float4*)&g_sums[(size_t)bidx * DIM];
#pragma unroll
    for (int q = 0; q < 8; q++) atomicAdd(&dst[lane + 32 * q], xr[q]);
    if (lane == 0) atomicAdd(&g_counts[bidx], 1);
}

// iteration 10: scatter directly into the per-batch output
__global__ void __launch_bounds__(256) refine_final(const float* __restrict__ X,
                                                    float* __restrict__ out) {
    int wip = (blockIdx.x * blockDim.x + threadIdx.x) >> 5;
    int lane = threadIdx.x & 31;
    float4 xr[8];
    int bidx = refine_pick(wip, lane, X, xr);
    int s = (wip >> 11) * N_CLU + bidx;
    float4* dst = (float4*)&out[(size_t)s * DIM];
#pragma unroll
    for (int q = 0; q < 8; q++) atomicAdd(&dst[lane + 32 * q], xr[q]);
    if (lane == 0) atomicAdd(&g_counts2[s], 1);
}

// ---------------- centroid update (+ csq + bf16 + zero for next iter) --------
__global__ void finalize_cent(void) {
    int c = blockIdx.x, t = threadIdx.x;
    int cnt = g_counts[c];
    float fc = (float)cnt;
    float4 sv = ((const float4*)&g_sums[(size_t)c * DIM])[t];
    float4 cv;
    if (cnt > 0) { cv.x = sv.x / fc; cv.y = sv.y / fc; cv.z = sv.z / fc; cv.w = sv.w / fc; }
    else cv = make_float4(0.f, 0.f, 0.f, 0.f);
    ((float4*)&g_cent[(size_t)c * DIM])[t] = cv;
    ((float4*)&g_sums[(size_t)c * DIM])[t] = make_float4(0.f, 0.f, 0.f, 0.f);
    __nv_bfloat16* cb = &g_cb0[(size_t)c * DIM + t * 4];
    cb[0] = __float2bfloat16_rn(cv.x); cb[1] = __float2bfloat16_rn(cv.y);
    cb[2] = __float2bfloat16_rn(cv.z); cb[3] = __float2bfloat16_rn(cv.w);

    __shared__ float red[256];
    __syncthreads();
    if (t == 0) g_counts[c] = 0;
    // csq: identical order to original csq_kernel (strided read of g_cent)
    const float* row = &g_cent[(size_t)c * DIM];
    float s = 0.f;
    for (int k = t; k < DIM; k += 256) { float v = row[k]; s += v * v; }
    red[t] = s; __syncthreads();
    for (int o = 128; o > 0; o >>= 1) {
        if (t < o) red[t] += red[t + o];
        __syncthreads();
    }
    if (t == 0) g_csq[c] = red[0];
}

// ---------------- output ----------------
__global__ void zero_out(float* __restrict__ out) {
    int t = blockIdx.x * blockDim.x + threadIdx.x;
    out[t] = 0.f;
    if (t < NBATCH * N_CLU) g_counts2[t] = 0;
    if (t < 16) g_unitv[t] = 0;   // reset work counters for next graph replay
}

__global__ void div_out(float* __restrict__ out) {
    int s = blockIdx.x;
    int cnt = g_counts2[s];
    if (cnt <= 0) return;
    float fc = (float)cnt;
    for (int k = threadIdx.x; k < DIM; k += 256)
        out[(size_t)s * DIM + k] /= fc;
}

// ---------------- driver ----------------
extern "C" void kernel_launch(void* const* d_in, const int* in_sizes, int n_in,
                              void* d_out, int out_size) {
    (void)in_sizes; (void)n_in; (void)out_size;
    const float* X = (const float*)d_in[0];
    float* out = (float*)d_out;

    // jax.random.key(42): partitionable threefry shuffle, 2 rounds
    u32 K1a, K1b, S1a, S1b, S2a, S2b;
    tf2x32(0u, 42u, 0u, 0u, K1a, K1b);
    tf2x32(0u, 42u, 0u, 1u, S1a, S1b);
    tf2x32(K1a, K1b, 0u, 1u, S2a, S2b);

    // round 1: bucket composites by top-10 bits; ranks resolved on demand
    gen_keys_kernel<<<N_PTS / 256, 256>>>(S1a, S1b);
    r1_zero<<<1, 1024>>>();
    r1_hist<<<N_PTS / 256, 256>>>();
    r1_scan<<<1, 1024>>>();
    r1_scatter<<<N_PTS / 256, 256>>>();
    // round 2: only the 512 smallest composites matter -> radix-select
    gen_keys_kernel<<<N_PTS / 256, 256>>>(S2a, S2b);
    sel_zero<<<1, 1024>>>();
    sel_hist<<<N_PTS / 256, 256>>>();
    sel_scan<<<1, 1024>>>();
    sel_compact<<<N_PTS / 256, 256>>>();
    sel_sort<<<1, 512>>>();

    gather_init<<<N_CLU, 256>>>(X);
    convert_x<<<N_PTS, 1024>>>(X);
    zero_sums<<<(N_CLU * DIM) / 256, 256>>>();

    for (int it = 0; it < 9; it++) {
        dist_hmma<<<DIST_GRID, 256>>>(it);
        refine_scatter<<<N_PTS * 32 / 256, 256>>>(X);
        finalize_cent<<<N_CLU, 256>>>();
    }
    // iteration 10: assignments feed the output directly
    dist_hmma<<<DIST_GRID, 256>>>(9);
    zero_out<<<(NBATCH * N_CLU * DIM) / 1024, 1024>>>(out);
    refine_final<<<N_PTS * 32 / 256, 256>>>(X, out);
    div_out<<<NBATCH * N_CLU, 256>>>(out);
}